// round 3
// baseline (speedup 1.0000x reference)
#include <cuda_runtime.h>

#define BB 8
#define NN 16384
#define DD 768
#define RR 3

// ---------------- scratch (device globals; no allocation) ----------------
__device__ float g_xr[BB*NN*RR];          // (B,N,R) projection, includes bias
__device__ float g_partial[16384*RR];     // per-block partial sums (pre-bias)
__device__ float g_G[BB*4];               // gate weights
__device__ float g_d1[BB*RR*64*64];
__device__ float g_d2[BB*RR*32*32];
__device__ float g_d3[BB*RR*16*16];
__device__ float g_c0[BB*RR*128*128];
__device__ float g_c1[BB*RR*64*64];
__device__ float g_c2[BB*RR*32*32];
__device__ float g_c3[BB*RR*16*16];
__device__ float g_mixed[BB*RR*128*128];  // (B,R,H,W)

// ---------------- kernel 1: xr = x @ Wd + bd, + deterministic partials ----
__global__ __launch_bounds__(256) void k_proj(const float* __restrict__ x,
                                              const float* __restrict__ Wd,
                                              const float* __restrict__ bd) {
    __shared__ float sWd[DD*RR];
    __shared__ float wp[8][3];
    int t = threadIdx.x;
    for (int i = t; i < DD*RR; i += 256) sWd[i] = Wd[i];
    __syncthreads();
    int warp = t >> 5, lane = t & 31;
    long row = (long)blockIdx.x * 8 + warp;       // 0..131071
    const float4* xp = (const float4*)(x + row * DD);
    float a0 = 0.f, a1 = 0.f, a2 = 0.f;
#pragma unroll
    for (int i = 0; i < 6; i++) {
        float4 v = xp[i*32 + lane];
        int d3 = (i*128 + lane*4) * 3;
        a0 += v.x*sWd[d3+0];  a1 += v.x*sWd[d3+1];  a2 += v.x*sWd[d3+2];
        a0 += v.y*sWd[d3+3];  a1 += v.y*sWd[d3+4];  a2 += v.y*sWd[d3+5];
        a0 += v.z*sWd[d3+6];  a1 += v.z*sWd[d3+7];  a2 += v.z*sWd[d3+8];
        a0 += v.w*sWd[d3+9];  a1 += v.w*sWd[d3+10]; a2 += v.w*sWd[d3+11];
    }
#pragma unroll
    for (int o = 16; o; o >>= 1) {
        a0 += __shfl_xor_sync(0xffffffffu, a0, o);
        a1 += __shfl_xor_sync(0xffffffffu, a1, o);
        a2 += __shfl_xor_sync(0xffffffffu, a2, o);
    }
    if (lane == 0) {
        g_xr[row*3+0] = a0 + bd[0];
        g_xr[row*3+1] = a1 + bd[1];
        g_xr[row*3+2] = a2 + bd[2];
        wp[warp][0] = a0; wp[warp][1] = a1; wp[warp][2] = a2;
    }
    __syncthreads();
    if (t == 0) {   // deterministic fixed-order block partial
        float p0 = 0.f, p1 = 0.f, p2 = 0.f;
        for (int w = 0; w < 8; w++) { p0 += wp[w][0]; p1 += wp[w][1]; p2 += wp[w][2]; }
        g_partial[blockIdx.x*3+0] = p0;
        g_partial[blockIdx.x*3+1] = p1;
        g_partial[blockIdx.x*3+2] = p2;
    }
}

// ---------------- kernel 2: mean + gating (noisy top-2 softmax) -----------
__global__ void k_gate(const float* __restrict__ noise,
                       const float* __restrict__ bd,
                       const float* __restrict__ Wg,
                       const float* __restrict__ Wn) {
    __shared__ float s_xa[24];
    int t = threadIdx.x;
    int c = t >> 5, lane = t & 31;
    if (c < 24) {                      // c = b*3 + r ; 2048 blocks per batch
        int b = c / 3, r = c - b*3;
        float s = 0.f;
        for (int k = lane; k < 2048; k += 32)
            s += g_partial[(b*2048 + k)*3 + r];
#pragma unroll
        for (int o = 16; o; o >>= 1) s += __shfl_xor_sync(0xffffffffu, s, o);
        if (lane == 0) s_xa[c] = s * (1.0f/16384.0f) + bd[r];
    }
    __syncthreads();
    if (t < 8) {
        int b = t;
        float x0 = s_xa[b*3], x1 = s_xa[b*3+1], x2 = s_xa[b*3+2];
        float hl[4];
#pragma unroll
        for (int e = 0; e < 4; e++) {
            float hg = x0*Wg[e] + x1*Wg[4+e] + x2*Wg[8+e];
            float z  = x0*Wn[e] + x1*Wn[4+e] + x2*Wn[8+e];
            float sp = fmaxf(z, 0.f) + log1pf(expf(-fabsf(z)));   // softplus (logaddexp)
            hl[e] = hg + noise[b*4+e]*sp;
        }
        int i1 = 0;
        for (int e = 1; e < 4; e++) if (hl[e] > hl[i1]) i1 = e;
        int i2 = -1;
        for (int e = 0; e < 4; e++) { if (e == i1) continue; if (i2 < 0 || hl[e] > hl[i2]) i2 = e; }
        float m  = hl[i1];
        float e2 = expf(hl[i2] - m);
        float inv = 1.f / (1.f + e2);
#pragma unroll
        for (int e = 0; e < 4; e++) g_G[b*4+e] = 0.f;
        g_G[b*4+i1] = inv;
        g_G[b*4+i2] = e2*inv;
    }
}

// ---------------- bilinear helpers (half-pixel, edge-clamped) -------------
__device__ __forceinline__ void lco(int i, int Sin, float scale,
                                    int& i0, int& i1, float& w) {
    // scale = Sin / Sout ; c = (i+0.5)*scale - 0.5 ; clamp-to-edge == jax norm.
    float c = (i + 0.5f) * scale - 0.5f;
    float f = floorf(c);
    w = c - f;
    i0 = (int)f; i1 = i0 + 1;
    if (i0 < 0) i0 = 0;
    if (i1 > Sin - 1) i1 = Sin - 1;
}

__device__ __forceinline__ float feat_at(int b, int r, int y, int x) {
    // feat[b,r,y,x] = xr[b, y*128+x, r]
    return g_xr[(((b << 14) + (y << 7) + x) * 3) + r];
}

// ---------------- kernel 3: downsample to 64/32/16 ------------------------
__global__ void k_down() {
    int idx = blockIdx.x * 256 + threadIdx.x;
    float* buf; int S, local;
    if      (idx < 98304)  { buf = g_d1; S = 64; local = idx; }
    else if (idx < 122880) { buf = g_d2; S = 32; local = idx - 98304; }
    else if (idx < 129024) { buf = g_d3; S = 16; local = idx - 122880; }
    else return;
    int br = local / (S*S); int pix = local - br*S*S;
    int y = pix / S, x = pix - y*S;
    int b = br / 3, r = br - b*3;
    float scale = 128.0f / (float)S;
    int y0, y1, x0, x1; float wy, wx;
    lco(y, 128, scale, y0, y1, wy);
    lco(x, 128, scale, x0, x1, wx);
    float v00 = feat_at(b, r, y0, x0), v01 = feat_at(b, r, y0, x1);
    float v10 = feat_at(b, r, y1, x0), v11 = feat_at(b, r, y1, x1);
    buf[local] = (1.f-wy)*((1.f-wx)*v00 + wx*v01) + wy*((1.f-wx)*v10 + wx*v11);
}

// ---------------- kernel 4: depthwise 3x3 (pad 1) at all scales -----------
__global__ void k_conv(const float* __restrict__ dwk, const float* __restrict__ dwb) {
    int idx = blockIdx.x * 256 + threadIdx.x;
    int S, local; const float* in = nullptr; float* out; bool from_xr = false;
    if      (idx < 393216) { S = 128; out = g_c0; local = idx;          from_xr = true; }
    else if (idx < 491520) { S = 64;  in = g_d1; out = g_c1; local = idx - 393216; }
    else if (idx < 516096) { S = 32;  in = g_d2; out = g_c2; local = idx - 491520; }
    else if (idx < 522240) { S = 16;  in = g_d3; out = g_c3; local = idx - 516096; }
    else return;
    int br = local / (S*S); int pix = local - br*S*S;
    int y = pix / S, x = pix - y*S;
    int b = br / 3, r = br - b*3;
    float acc = dwb[r];
#pragma unroll
    for (int dy = 0; dy < 3; dy++) {
        int yy = y + dy - 1; if (yy < 0 || yy >= S) continue;
#pragma unroll
        for (int dx = 0; dx < 3; dx++) {
            int xx = x + dx - 1; if (xx < 0 || xx >= S) continue;
            float v = from_xr ? feat_at(b, r, yy, xx) : in[br*S*S + yy*S + xx];
            acc += v * dwk[r*9 + dy*3 + dx];
        }
    }
    out[local] = acc;
}

// ---------------- kernel 5: mixed = sum_j G_j * upsample(conv_j) ----------
__device__ __forceinline__ float bilerp_up(const float* p, int S, int y, int x) {
    float scale = (float)S / 128.0f;
    int y0, y1, x0, x1; float wy, wx;
    lco(y, S, scale, y0, y1, wy);
    lco(x, S, scale, x0, x1, wx);
    float v00 = p[y0*S + x0], v01 = p[y0*S + x1];
    float v10 = p[y1*S + x0], v11 = p[y1*S + x1];
    return (1.f-wy)*((1.f-wx)*v00 + wx*v01) + wy*((1.f-wx)*v10 + wx*v11);
}

__global__ void k_combine() {
    int idx = blockIdx.x * 256 + threadIdx.x;   // < 393216 exactly
    int br = idx >> 14; int pix = idx & 16383;
    int y = pix >> 7, x = pix & 127;
    int b = br / 3;
    float v = g_G[b*4 + 0] * g_c0[idx]
            + g_G[b*4 + 1] * bilerp_up(g_c1 + br*4096, 64, y, x)
            + g_G[b*4 + 2] * bilerp_up(g_c2 + br*1024, 32, y, x)
            + g_G[b*4 + 3] * bilerp_up(g_c3 + br*256,  16, y, x);
    g_mixed[idx] = v;
}

// ---------------- kernel 6: out = x + mixed @ Wu + bu ---------------------
__global__ __launch_bounds__(256) void k_final(const float* __restrict__ x,
                                               const float* __restrict__ Wu,
                                               const float* __restrict__ bu,
                                               float* __restrict__ out) {
    __shared__ float sW[3*768 + 768];
    int t = threadIdx.x;
    for (int i = t; i < 2304; i += 256) sW[i] = Wu[i];
    for (int i = t; i < 768;  i += 256) sW[2304 + i] = bu[i];
    __syncthreads();
    int warp = t >> 5, lane = t & 31;
    long row = (long)blockIdx.x * 8 + warp;
    int b = (int)(row >> 14); int n = (int)(row & 16383);
    float m0 = g_mixed[(b*3 + 0) * 16384 + n];
    float m1 = g_mixed[(b*3 + 1) * 16384 + n];
    float m2 = g_mixed[(b*3 + 2) * 16384 + n];
    const float4* xp = (const float4*)(x + row * DD);
    float4* op = (float4*)(out + row * DD);
#pragma unroll
    for (int i = 0; i < 6; i++) {
        int d = i*128 + lane*4;
        float4 v = xp[i*32 + lane];
        float4 o;
        o.x = v.x + m0*sW[d  ] + m1*sW[768+d  ] + m2*sW[1536+d  ] + sW[2304+d  ];
        o.y = v.y + m0*sW[d+1] + m1*sW[768+d+1] + m2*sW[1536+d+1] + sW[2304+d+1];
        o.z = v.z + m0*sW[d+2] + m1*sW[768+d+2] + m2*sW[1536+d+2] + sW[2304+d+2];
        o.w = v.w + m0*sW[d+3] + m1*sW[768+d+3] + m2*sW[1536+d+3] + sW[2304+d+3];
        op[i*32 + lane] = o;
    }
}

// ---------------- launch --------------------------------------------------
extern "C" void kernel_launch(void* const* d_in, const int* in_sizes, int n_in,
                              void* d_out, int out_size) {
    const float* x     = (const float*)d_in[0];
    const float* noise = (const float*)d_in[1];
    const float* Wd    = (const float*)d_in[2];
    const float* bd    = (const float*)d_in[3];
    const float* Wu    = (const float*)d_in[4];
    const float* bu    = (const float*)d_in[5];
    const float* Wg    = (const float*)d_in[6];
    const float* Wn    = (const float*)d_in[7];
    const float* dwk   = (const float*)d_in[8];
    const float* dwb   = (const float*)d_in[9];
    float* out = (float*)d_out;

    k_proj   <<<16384, 256>>>(x, Wd, bd);
    k_gate   <<<1, 768>>>(noise, bd, Wg, Wn);
    k_down   <<<504, 256>>>();        // 129024 threads exactly
    k_conv   <<<2040, 256>>>(dwk, dwb); // 522240 threads exactly
    k_combine<<<1536, 256>>>();       // 393216 threads exactly
    k_final  <<<16384, 256>>>(x, Wu, bu, out);
}

// round 4
// speedup vs baseline: 1.0237x; 1.0237x over previous
#include <cuda_runtime.h>

#define BB 8
#define NN 16384
#define DD 768
#define RR 3

// ---------------- scratch (device globals; no allocation) ----------------
__device__ float g_feat[BB*RR*NN];        // planar (B,R,128,128), includes bias
__device__ float g_partial[16384*RR];     // per-block partial sums (pre-bias)
__device__ float g_G[BB*4];               // gate weights
__device__ float g_c0[BB*RR*128*128];
__device__ float g_c1[BB*RR*64*64];
__device__ float g_c2[BB*RR*32*32];
__device__ float g_c3[BB*RR*16*16];

// ---------------- kernel 1: feat = x @ Wd + bd (planar) + partials --------
__global__ __launch_bounds__(256) void k_proj(const float* __restrict__ x,
                                              const float* __restrict__ Wd,
                                              const float* __restrict__ bd) {
    __shared__ float sWd[DD*RR];          // Wd[d*3+r], 16B-aligned vec4 reads
    __shared__ float wp[8][3];
    int t = threadIdx.x;
    for (int i = t; i < DD*RR; i += 256) sWd[i] = Wd[i];
    __syncthreads();
    int warp = t >> 5, lane = t & 31;
    long row = (long)blockIdx.x * 8 + warp;       // 0..131071
    const float4* xp  = (const float4*)(x + row * DD);
    const float4* sW4 = (const float4*)sWd;
    float a0 = 0.f, a1 = 0.f, a2 = 0.f;
#pragma unroll
    for (int i = 0; i < 6; i++) {
        float4 v = xp[i*32 + lane];
        int base = 3 * (i*32 + lane);             // float4 index; stride-48B: conflict-free
        float4 w0 = sW4[base], w1 = sW4[base+1], w2 = sW4[base+2];
        a0 += v.x*w0.x; a1 += v.x*w0.y; a2 += v.x*w0.z;
        a0 += v.y*w0.w; a1 += v.y*w1.x; a2 += v.y*w1.y;
        a0 += v.z*w1.z; a1 += v.z*w1.w; a2 += v.z*w2.x;
        a0 += v.w*w2.y; a1 += v.w*w2.z; a2 += v.w*w2.w;
    }
#pragma unroll
    for (int o = 16; o; o >>= 1) {
        a0 += __shfl_xor_sync(0xffffffffu, a0, o);
        a1 += __shfl_xor_sync(0xffffffffu, a1, o);
        a2 += __shfl_xor_sync(0xffffffffu, a2, o);
    }
    if (lane == 0) {
        int b = (int)(row >> 14), n = (int)(row & 16383);
        g_feat[(b*3 + 0)*NN + n] = a0 + bd[0];
        g_feat[(b*3 + 1)*NN + n] = a1 + bd[1];
        g_feat[(b*3 + 2)*NN + n] = a2 + bd[2];
        wp[warp][0] = a0; wp[warp][1] = a1; wp[warp][2] = a2;
    }
    __syncthreads();
    if (t == 0) {   // deterministic fixed-order block partial
        float p0 = 0.f, p1 = 0.f, p2 = 0.f;
        for (int w = 0; w < 8; w++) { p0 += wp[w][0]; p1 += wp[w][1]; p2 += wp[w][2]; }
        g_partial[blockIdx.x*3+0] = p0;
        g_partial[blockIdx.x*3+1] = p1;
        g_partial[blockIdx.x*3+2] = p2;
    }
}

// ---------------- kernel 2: mean + gating (noisy top-2 softmax) -----------
__global__ void k_gate(const float* __restrict__ noise,
                       const float* __restrict__ bd,
                       const float* __restrict__ Wg,
                       const float* __restrict__ Wn) {
    __shared__ float s_xa[24];
    int t = threadIdx.x;
    int c = t >> 5, lane = t & 31;
    if (c < 24) {                      // c = b*3 + r ; 2048 blocks per batch
        int b = c / 3, r = c - b*3;
        float s = 0.f;
        for (int k = lane; k < 2048; k += 32)
            s += g_partial[(b*2048 + k)*3 + r];
#pragma unroll
        for (int o = 16; o; o >>= 1) s += __shfl_xor_sync(0xffffffffu, s, o);
        if (lane == 0) s_xa[c] = s * (1.0f/16384.0f) + bd[r];
    }
    __syncthreads();
    if (t < 8) {
        int b = t;
        float x0 = s_xa[b*3], x1 = s_xa[b*3+1], x2 = s_xa[b*3+2];
        float hl[4];
#pragma unroll
        for (int e = 0; e < 4; e++) {
            float hg = x0*Wg[e] + x1*Wg[4+e] + x2*Wg[8+e];
            float z  = x0*Wn[e] + x1*Wn[4+e] + x2*Wn[8+e];
            float sp = fmaxf(z, 0.f) + log1pf(expf(-fabsf(z)));   // softplus
            hl[e] = hg + noise[b*4+e]*sp;
        }
        int i1 = 0;
        for (int e = 1; e < 4; e++) if (hl[e] > hl[i1]) i1 = e;
        int i2 = -1;
        for (int e = 0; e < 4; e++) { if (e == i1) continue; if (i2 < 0 || hl[e] > hl[i2]) i2 = e; }
        float m  = hl[i1];
        float e2 = expf(hl[i2] - m);
        float inv = 1.f / (1.f + e2);
#pragma unroll
        for (int e = 0; e < 4; e++) g_G[b*4+e] = 0.f;
        g_G[b*4+i1] = inv;
        g_G[b*4+i2] = e2*inv;
    }
}

// ---------------- bilinear helpers (half-pixel, edge-clamped) -------------
__device__ __forceinline__ void lco(int i, int Sin, float scale,
                                    int& i0, int& i1, float& w) {
    float c = (i + 0.5f) * scale - 0.5f;
    float f = floorf(c);
    w = c - f;
    i0 = (int)f; i1 = i0 + 1;
    if (i0 < 0) i0 = 0;
    if (i1 > Sin - 1) i1 = Sin - 1;
}

// downsample plane (128x128) -> S at (y,x), on the fly
__device__ __forceinline__ float dval(const float* __restrict__ p, int S, int y, int x) {
    float scale = 128.0f / (float)S;
    int y0, y1, x0, x1; float wy, wx;
    lco(y, 128, scale, y0, y1, wy);
    lco(x, 128, scale, x0, x1, wx);
    float v00 = p[(y0<<7)+x0], v01 = p[(y0<<7)+x1];
    float v10 = p[(y1<<7)+x0], v11 = p[(y1<<7)+x1];
    return (1.f-wy)*((1.f-wx)*v00 + wx*v01) + wy*((1.f-wx)*v10 + wx*v11);
}

// ---------------- kernel 3: fused downsample + depthwise 3x3 --------------
__global__ void k_conv(const float* __restrict__ dwk, const float* __restrict__ dwb) {
    int idx = blockIdx.x * 256 + threadIdx.x;
    int S, local; float* out;
    if      (idx < 393216) { S = 128; out = g_c0; local = idx; }
    else if (idx < 491520) { S = 64;  out = g_c1; local = idx - 393216; }
    else if (idx < 516096) { S = 32;  out = g_c2; local = idx - 491520; }
    else if (idx < 522240) { S = 16;  out = g_c3; local = idx - 516096; }
    else return;
    int br = local / (S*S); int pix = local - br*S*S;
    int y = pix / S, x = pix - y*S;
    int r = br % 3;
    const float* plane = g_feat + br * NN;
    float acc = dwb[r];
#pragma unroll
    for (int dy = 0; dy < 3; dy++) {
        int yy = y + dy - 1; if (yy < 0 || yy >= S) continue;
#pragma unroll
        for (int dx = 0; dx < 3; dx++) {
            int xx = x + dx - 1; if (xx < 0 || xx >= S) continue;
            float v = (S == 128) ? plane[(yy<<7)+xx] : dval(plane, S, yy, xx);
            acc += v * dwk[r*9 + dy*3 + dx];
        }
    }
    out[local] = acc;
}

// upsample S -> 128 at (y,x)
__device__ __forceinline__ float bilerp_up(const float* __restrict__ p, int S, int y, int x) {
    float scale = (float)S / 128.0f;
    int y0, y1, x0, x1; float wy, wx;
    lco(y, S, scale, y0, y1, wy);
    lco(x, S, scale, x0, x1, wx);
    float v00 = p[y0*S + x0], v01 = p[y0*S + x1];
    float v10 = p[y1*S + x0], v11 = p[y1*S + x1];
    return (1.f-wy)*((1.f-wx)*v00 + wx*v01) + wy*((1.f-wx)*v10 + wx*v11);
}

// ---------------- kernel 4: out = x + (sum_j G_j up(conv_j)) @ Wu + bu ----
__global__ __launch_bounds__(256) void k_final(const float* __restrict__ x,
                                               const float* __restrict__ Wu,
                                               const float* __restrict__ bu,
                                               float* __restrict__ out) {
    __shared__ float4 sW[576];   // Wu (3,768) row-major, vec4
    __shared__ float4 sB[192];   // bu
    int t = threadIdx.x;
    const float4* Wu4 = (const float4*)Wu;
    const float4* bu4 = (const float4*)bu;
    for (int i = t; i < 576; i += 256) sW[i] = Wu4[i];
    for (int i = t; i < 192; i += 256) sB[i] = bu4[i];
    __syncthreads();
    int warp = t >> 5, lane = t & 31;
    long row = (long)blockIdx.x * 8 + warp;
    int b = (int)(row >> 14); int n = (int)(row & 16383);
    int y = n >> 7, xx = n & 127;
    // lanes 0-2 each compute one mixed channel, then broadcast
    float m = 0.f;
    if (lane < 3) {
        int br = b*3 + lane;
        float G0 = g_G[b*4+0], G1 = g_G[b*4+1], G2 = g_G[b*4+2], G3 = g_G[b*4+3];
        m = G0 * g_c0[br*16384 + n]
          + G1 * bilerp_up(g_c1 + br*4096, 64, y, xx)
          + G2 * bilerp_up(g_c2 + br*1024, 32, y, xx)
          + G3 * bilerp_up(g_c3 + br*256,  16, y, xx);
    }
    float m0 = __shfl_sync(0xffffffffu, m, 0);
    float m1 = __shfl_sync(0xffffffffu, m, 1);
    float m2 = __shfl_sync(0xffffffffu, m, 2);
    const float4* xp = (const float4*)(x + row * DD);
    float4* op = (float4*)(out + row * DD);
#pragma unroll
    for (int i = 0; i < 6; i++) {
        int q = i*32 + lane;                  // float4 index within 768
        float4 v  = xp[q];
        float4 w0 = sW[q], w1 = sW[192 + q], w2 = sW[384 + q];
        float4 bb = sB[q];
        float4 o;
        o.x = v.x + m0*w0.x + m1*w1.x + m2*w2.x + bb.x;
        o.y = v.y + m0*w0.y + m1*w1.y + m2*w2.y + bb.y;
        o.z = v.z + m0*w0.z + m1*w1.z + m2*w2.z + bb.z;
        o.w = v.w + m0*w0.w + m1*w1.w + m2*w2.w + bb.w;
        op[q] = o;
    }
}

// ---------------- launch --------------------------------------------------
extern "C" void kernel_launch(void* const* d_in, const int* in_sizes, int n_in,
                              void* d_out, int out_size) {
    const float* x     = (const float*)d_in[0];
    const float* noise = (const float*)d_in[1];
    const float* Wd    = (const float*)d_in[2];
    const float* bd    = (const float*)d_in[3];
    const float* Wu    = (const float*)d_in[4];
    const float* bu    = (const float*)d_in[5];
    const float* Wg    = (const float*)d_in[6];
    const float* Wn    = (const float*)d_in[7];
    const float* dwk   = (const float*)d_in[8];
    const float* dwb   = (const float*)d_in[9];
    float* out = (float*)d_out;

    k_proj <<<16384, 256>>>(x, Wd, bd);
    k_gate <<<1, 768>>>(noise, bd, Wg, Wn);
    k_conv <<<2040, 256>>>(dwk, dwb);   // 522240 threads: fused down+conv, all scales
    k_final<<<16384, 256>>>(x, Wu, bu, out);
}